// round 10
// baseline (speedup 1.0000x reference)
#include <cuda_runtime.h>
#include <cstdint>

// ERGCN layer:
//   msg[k] = h[src[k]] * weight[rel[k]] + e[k] * attention[rel[k]]   (D=64)
//   out    = h + segment_sum(msg, dst)
//
// Inputs: h[N*64] f32, e[E*64] f32, weight[R*64] f32, attention[R*64] f32,
//         src[E] i32, dst[E] i32, rel[E] i32. Output: [N*64] f32.

#define D 64
#define D4 (D / 4)        // 16 float4 per row
#define TPB 256
#define TPE 8             // threads per edge; each handles chunks t and t+8

// e stream: bypass L1 allocation (zero reuse; keep tables/h resident in L1).
__device__ __forceinline__ float4 ldg_stream(const float4* p) {
    float4 v;
    asm("ld.global.nc.L1::no_allocate.v4.f32 {%0,%1,%2,%3}, [%4];"
        : "=f"(v.x), "=f"(v.y), "=f"(v.z), "=f"(v.w) : "l"(p));
    return v;
}

// ---------------------------------------------------------------------------
// Kernel 1: out = h (d_out is poisoned before timing)
// ---------------------------------------------------------------------------
__global__ void init_out_kernel(float4* __restrict__ out,
                                const float4* __restrict__ h,
                                int n4) {
    int i = blockIdx.x * blockDim.x + threadIdx.x;
    if (i < n4) out[i] = h[i];
}

// ---------------------------------------------------------------------------
// Kernel 2: 8 threads per edge, 2 float4 chunks per thread.
// __launch_bounds__(256, 8): force 32-reg target -> 100% theoretical occ.
// Body split so the m0 half can retire before m1's table loads, giving
// ptxas a natural <=32-reg schedule instead of spilling.
// ---------------------------------------------------------------------------
__global__ void __launch_bounds__(TPB, 8)
edge_kernel(const float* __restrict__ h,
            const float* __restrict__ e,
            const float4* __restrict__ w_g,
            const float4* __restrict__ a_g,
            const int* __restrict__ src,
            const int* __restrict__ dst,
            const int* __restrict__ rel,
            float* __restrict__ out,
            int E_) {
    const int gid = blockIdx.x * TPB + threadIdx.x;
    const int k   = gid >> 3;          // edge index
    const int t   = gid & 7;           // chunk index (handles t and t+8)
    if (k >= E_) return;

    const int s_ = __ldg(src + k);
    const int d_ = __ldg(dst + k);
    const int r_ = __ldg(rel + k);

    const float4* ep = (const float4*)(e + (size_t)k  * D) + t;
    const float4* hp = (const float4*)(h + (size_t)s_ * D) + t;
    const float4* wp = w_g + r_ * D4 + t;
    const float4* ap = a_g + r_ * D4 + t;

    // Front-batch the long-latency streams for both halves.
    const float4 ev0 = ldg_stream(ep);
    const float4 ev1 = ldg_stream(ep + 8);
    const float4 hv0 = __ldg(hp);
    const float4 hv1 = __ldg(hp + 8);

    // Half 0: table loads (L1-hot), compute, scatter.
    {
        const float4 wv0 = __ldg(wp);
        const float4 av0 = __ldg(ap);
        float4 m0;
        m0.x = fmaf(hv0.x, wv0.x, ev0.x * av0.x);
        m0.y = fmaf(hv0.y, wv0.y, ev0.y * av0.y);
        m0.z = fmaf(hv0.z, wv0.z, ev0.z * av0.z);
        m0.w = fmaf(hv0.w, wv0.w, ev0.w * av0.w);
        float* o = out + (size_t)d_ * D + t * 4;
        asm volatile("red.global.add.v4.f32 [%0], {%1, %2, %3, %4};"
                     :: "l"(o), "f"(m0.x), "f"(m0.y), "f"(m0.z), "f"(m0.w)
                     : "memory");
    }

    // Half 1.
    {
        const float4 wv1 = __ldg(wp + 8);
        const float4 av1 = __ldg(ap + 8);
        float4 m1;
        m1.x = fmaf(hv1.x, wv1.x, ev1.x * av1.x);
        m1.y = fmaf(hv1.y, wv1.y, ev1.y * av1.y);
        m1.z = fmaf(hv1.z, wv1.z, ev1.z * av1.z);
        m1.w = fmaf(hv1.w, wv1.w, ev1.w * av1.w);
        float* o = out + (size_t)d_ * D + t * 4 + 32;
        asm volatile("red.global.add.v4.f32 [%0], {%1, %2, %3, %4};"
                     :: "l"(o), "f"(m1.x), "f"(m1.y), "f"(m1.z), "f"(m1.w)
                     : "memory");
    }
}

extern "C" void kernel_launch(void* const* d_in, const int* in_sizes, int n_in,
                              void* d_out, int out_size) {
    const float* h   = (const float*)d_in[0];
    const float* e   = (const float*)d_in[1];
    const float* wgt = (const float*)d_in[2];
    const float* att = (const float*)d_in[3];
    const int*   src = (const int*)d_in[4];
    const int*   dst = (const int*)d_in[5];
    const int*   rel = (const int*)d_in[6];
    float*       out = (float*)d_out;

    const int ND = in_sizes[0];      // N * 64
    const int E_ = in_sizes[4];      // edge count

    // out = h
    {
        int n4 = ND / 4;
        init_out_kernel<<<(n4 + TPB - 1) / TPB, TPB>>>(
            (float4*)out, (const float4*)h, n4);
    }

    // 8 threads per edge
    {
        long long total = (long long)E_ * TPE;
        int blocks = (int)((total + TPB - 1) / TPB);
        edge_kernel<<<blocks, TPB>>>(h, e, (const float4*)wgt,
                                     (const float4*)att,
                                     src, dst, rel, out, E_);
    }
}

// round 12
// speedup vs baseline: 1.2776x; 1.2776x over previous
#include <cuda_runtime.h>
#include <cstdint>

// ERGCN layer:
//   msg[k] = h[src[k]] * weight[rel[k]] + e[k] * attention[rel[k]]   (D=64)
//   out    = h + segment_sum(msg, dst)
//
// Inputs: h[N*64] f32, e[E*64] f32, weight[R*64] f32, attention[R*64] f32,
//         src[E] i32, dst[E] i32, rel[E] i32. Output: [N*64] f32.

#define D 64
#define D4 (D / 4)          // 16 float4 per row
#define TPB 256
#define EPB (TPB / 8)       // 32 edges per block-iteration (8 threads/edge)
#define NBLOCKS (148 * 3)   // persistent: one wave at 3 CTAs/SM

// e stream: bypass L1 allocation (zero reuse; keep tables/h resident in L1).
__device__ __forceinline__ float4 ldg_stream(const float4* p) {
    float4 v;
    asm("ld.global.nc.L1::no_allocate.v4.f32 {%0,%1,%2,%3}, [%4];"
        : "=f"(v.x), "=f"(v.y), "=f"(v.z), "=f"(v.w) : "l"(p));
    return v;
}

// ---------------------------------------------------------------------------
// Kernel 1: out = h (d_out is poisoned before timing)
// ---------------------------------------------------------------------------
__global__ void init_out_kernel(float4* __restrict__ out,
                                const float4* __restrict__ h,
                                int n4) {
    int i = blockIdx.x * blockDim.x + threadIdx.x;
    if (i < n4) out[i] = h[i];
}

// ---------------------------------------------------------------------------
// Kernel 2: 8 threads/edge, persistent grid-stride, 2-deep software pipeline.
// At iter i: issue idx_{i+1} + e_{i+1} (independent), then h/w/a_i whose
// indices resolved one full iteration ago -> DRAM latency of e and the idx
// chain are hidden; only the L2 h-gather remains exposed.
// ---------------------------------------------------------------------------
__global__ void __launch_bounds__(TPB)
edge_kernel(const float* __restrict__ h,
            const float* __restrict__ e,
            const float4* __restrict__ w_g,
            const float4* __restrict__ a_g,
            const int* __restrict__ src,
            const int* __restrict__ dst,
            const int* __restrict__ rel,
            float* __restrict__ out,
            int E_) {
    const int t      = threadIdx.x & 7;            // chunk (t and t+8)
    const int group  = threadIdx.x >> 3;           // edge within block tile
    const int stride = NBLOCKS * EPB;

    int k = blockIdx.x * EPB + group;
    if (k >= E_) return;

    // Prologue: stage iteration 0's indices and e-stream.
    int s_ = __ldg(src + k);
    int d_ = __ldg(dst + k);
    int r_ = __ldg(rel + k);
    const float4* ep = (const float4*)(e + (size_t)k * D) + t;
    float4 ev0 = ldg_stream(ep);
    float4 ev1 = ldg_stream(ep + 8);

    while (true) {
        const int kn = k + stride;
        const bool more = kn < E_;
        const int kc = more ? kn : k;              // clamp: harmless reload

        // --- Prefetch next iteration (independent of current) ---
        const int sn = __ldg(src + kc);
        const int dn = __ldg(dst + kc);
        const int rn = __ldg(rel + kc);
        const float4* epn = (const float4*)(e + (size_t)kc * D) + t;
        const float4 en0 = ldg_stream(epn);
        const float4 en1 = ldg_stream(epn + 8);

        // --- Current iteration gathers (indices long resolved) ---
        const float4* hp = (const float4*)(h + (size_t)s_ * D) + t;
        const float4* wp = w_g + r_ * D4 + t;
        const float4* ap = a_g + r_ * D4 + t;
        const float4 hv0 = __ldg(hp);
        const float4 hv1 = __ldg(hp + 8);
        const float4 wv0 = __ldg(wp);
        const float4 wv1 = __ldg(wp + 8);
        const float4 av0 = __ldg(ap);
        const float4 av1 = __ldg(ap + 8);

        float4 m0, m1;
        m0.x = fmaf(hv0.x, wv0.x, ev0.x * av0.x);
        m0.y = fmaf(hv0.y, wv0.y, ev0.y * av0.y);
        m0.z = fmaf(hv0.z, wv0.z, ev0.z * av0.z);
        m0.w = fmaf(hv0.w, wv0.w, ev0.w * av0.w);
        m1.x = fmaf(hv1.x, wv1.x, ev1.x * av1.x);
        m1.y = fmaf(hv1.y, wv1.y, ev1.y * av1.y);
        m1.z = fmaf(hv1.z, wv1.z, ev1.z * av1.z);
        m1.w = fmaf(hv1.w, wv1.w, ev1.w * av1.w);

        float* o = out + (size_t)d_ * D + t * 4;
        asm volatile("red.global.add.v4.f32 [%0], {%1, %2, %3, %4};"
                     :: "l"(o), "f"(m0.x), "f"(m0.y), "f"(m0.z), "f"(m0.w)
                     : "memory");
        asm volatile("red.global.add.v4.f32 [%0], {%1, %2, %3, %4};"
                     :: "l"(o + 32), "f"(m1.x), "f"(m1.y), "f"(m1.z), "f"(m1.w)
                     : "memory");

        if (!more) break;

        // Rotate pipeline state.
        k = kn; s_ = sn; d_ = dn; r_ = rn; ev0 = en0; ev1 = en1;
    }
}

extern "C" void kernel_launch(void* const* d_in, const int* in_sizes, int n_in,
                              void* d_out, int out_size) {
    const float* h   = (const float*)d_in[0];
    const float* e   = (const float*)d_in[1];
    const float* wgt = (const float*)d_in[2];
    const float* att = (const float*)d_in[3];
    const int*   src = (const int*)d_in[4];
    const int*   dst = (const int*)d_in[5];
    const int*   rel = (const int*)d_in[6];
    float*       out = (float*)d_out;

    const int ND = in_sizes[0];      // N * 64
    const int E_ = in_sizes[4];      // edge count

    // out = h
    {
        int n4 = ND / 4;
        init_out_kernel<<<(n4 + TPB - 1) / TPB, TPB>>>(
            (float4*)out, (const float4*)h, n4);
    }

    // persistent pipelined edge kernel
    edge_kernel<<<NBLOCKS, TPB>>>(h, e, (const float4*)wgt,
                                  (const float4*)att,
                                  src, dst, rel, out, E_);
}

// round 13
// speedup vs baseline: 1.5964x; 1.2495x over previous
#include <cuda_runtime.h>
#include <cstdint>

// ERGCN layer:
//   msg[k] = h[src[k]] * weight[rel[k]] + e[k] * attention[rel[k]]   (D=64)
//   out    = h + segment_sum(msg, dst)
//
// Inputs: h[N*64] f32, e[E*64] f32, weight[R*64] f32, attention[R*64] f32,
//         src[E] i32, dst[E] i32, rel[E] i32. Output: [N*64] f32.

#define D 64
#define D4 (D / 4)          // 16 float4 per row
#define TPB 256
#define EPB (TPB / 8)       // 32 edges per block-iteration (8 threads/edge)
#define NBLOCKS (148 * 5)   // persistent: one wave at 5 CTAs/SM (48 regs/thread)

// e stream: bypass L1 allocation (zero reuse; keep tables/h resident in L1).
__device__ __forceinline__ float4 ldg_stream(const float4* p) {
    float4 v;
    asm("ld.global.nc.L1::no_allocate.v4.f32 {%0,%1,%2,%3}, [%4];"
        : "=f"(v.x), "=f"(v.y), "=f"(v.z), "=f"(v.w) : "l"(p));
    return v;
}

// ---------------------------------------------------------------------------
// Kernel 1: out = h (d_out is poisoned before timing)
// ---------------------------------------------------------------------------
__global__ void init_out_kernel(float4* __restrict__ out,
                                const float4* __restrict__ h,
                                int n4) {
    int i = blockIdx.x * blockDim.x + threadIdx.x;
    if (i < n4) out[i] = h[i];
}

// ---------------------------------------------------------------------------
// Kernel 2: 8 threads/edge, persistent grid-stride, 2-deep software pipeline.
// At iter i: issue idx_{i+1} + e_{i+1} (independent), then h/w/a_i whose
// indices resolved a full iteration ago -> idx chain + DRAM e-latency hidden.
// 5 CTAs/SM x ~19 outstanding LDG/warp ≈ 760 loads in flight per SM.
// ---------------------------------------------------------------------------
__global__ void __launch_bounds__(TPB)
edge_kernel(const float* __restrict__ h,
            const float* __restrict__ e,
            const float4* __restrict__ w_g,
            const float4* __restrict__ a_g,
            const int* __restrict__ src,
            const int* __restrict__ dst,
            const int* __restrict__ rel,
            float* __restrict__ out,
            int E_) {
    const int t      = threadIdx.x & 7;            // chunk (t and t+8)
    const int group  = threadIdx.x >> 3;           // edge within block tile
    const int stride = NBLOCKS * EPB;

    int k = blockIdx.x * EPB + group;
    if (k >= E_) return;

    // Prologue: stage iteration 0's indices and e-stream.
    int s_ = __ldg(src + k);
    int d_ = __ldg(dst + k);
    int r_ = __ldg(rel + k);
    const float4* ep = (const float4*)(e + (size_t)k * D) + t;
    float4 ev0 = ldg_stream(ep);
    float4 ev1 = ldg_stream(ep + 8);

    while (true) {
        const int kn = k + stride;
        const bool more = kn < E_;
        const int kc = more ? kn : k;              // clamp: harmless reload

        // --- Prefetch next iteration (independent of current) ---
        const int sn = __ldg(src + kc);
        const int dn = __ldg(dst + kc);
        const int rn = __ldg(rel + kc);
        const float4* epn = (const float4*)(e + (size_t)kc * D) + t;
        const float4 en0 = ldg_stream(epn);
        const float4 en1 = ldg_stream(epn + 8);

        // --- Current iteration gathers (indices long resolved) ---
        const float4* hp = (const float4*)(h + (size_t)s_ * D) + t;
        const float4* wp = w_g + r_ * D4 + t;
        const float4* ap = a_g + r_ * D4 + t;
        const float4 hv0 = __ldg(hp);
        const float4 hv1 = __ldg(hp + 8);
        const float4 wv0 = __ldg(wp);
        const float4 wv1 = __ldg(wp + 8);
        const float4 av0 = __ldg(ap);
        const float4 av1 = __ldg(ap + 8);

        float4 m0, m1;
        m0.x = fmaf(hv0.x, wv0.x, ev0.x * av0.x);
        m0.y = fmaf(hv0.y, wv0.y, ev0.y * av0.y);
        m0.z = fmaf(hv0.z, wv0.z, ev0.z * av0.z);
        m0.w = fmaf(hv0.w, wv0.w, ev0.w * av0.w);
        m1.x = fmaf(hv1.x, wv1.x, ev1.x * av1.x);
        m1.y = fmaf(hv1.y, wv1.y, ev1.y * av1.y);
        m1.z = fmaf(hv1.z, wv1.z, ev1.z * av1.z);
        m1.w = fmaf(hv1.w, wv1.w, ev1.w * av1.w);

        float* o = out + (size_t)d_ * D + t * 4;
        asm volatile("red.global.add.v4.f32 [%0], {%1, %2, %3, %4};"
                     :: "l"(o), "f"(m0.x), "f"(m0.y), "f"(m0.z), "f"(m0.w)
                     : "memory");
        asm volatile("red.global.add.v4.f32 [%0], {%1, %2, %3, %4};"
                     :: "l"(o + 32), "f"(m1.x), "f"(m1.y), "f"(m1.z), "f"(m1.w)
                     : "memory");

        if (!more) break;

        // Rotate pipeline state.
        k = kn; s_ = sn; d_ = dn; r_ = rn; ev0 = en0; ev1 = en1;
    }
}

extern "C" void kernel_launch(void* const* d_in, const int* in_sizes, int n_in,
                              void* d_out, int out_size) {
    const float* h   = (const float*)d_in[0];
    const float* e   = (const float*)d_in[1];
    const float* wgt = (const float*)d_in[2];
    const float* att = (const float*)d_in[3];
    const int*   src = (const int*)d_in[4];
    const int*   dst = (const int*)d_in[5];
    const int*   rel = (const int*)d_in[6];
    float*       out = (float*)d_out;

    const int ND = in_sizes[0];      // N * 64
    const int E_ = in_sizes[4];      // edge count

    // out = h
    {
        int n4 = ND / 4;
        init_out_kernel<<<(n4 + TPB - 1) / TPB, TPB>>>(
            (float4*)out, (const float4*)h, n4);
    }

    // persistent pipelined edge kernel, one full wave at 5 CTAs/SM
    edge_kernel<<<NBLOCKS, TPB>>>(h, e, (const float4*)wgt,
                                  (const float4*)att,
                                  src, dst, rel, out, E_);
}